// round 4
// baseline (speedup 1.0000x reference)
#include <cuda_runtime.h>
#include <math.h>

#define B_    64
#define S_    512
#define E_    256
#define H_    512
#define NCTA  128
#define NTHR  320

// ---------------- device scratch (static; no allocation) ----------------
__device__ float g_upT[(long long)S_ * 2048 * B_];   // [s][g][b]  256 MB
__device__ float g_decT[S_ * B_];                    // [s][b]
__device__ float g_h[2][H_ * B_];                    // [par][u][b]
__device__ float g_c[2][H_ * B_];
__device__ volatile unsigned g_bar_gen;
__device__ unsigned g_bar_cnt;

// ---------------- helpers ----------------
__device__ __forceinline__ float sigf(float x) { return 1.0f / (1.0f + __expf(-x)); }
__device__ __forceinline__ float tanh_fast(float x) {
    float e = __expf(2.0f * x);
    return 1.0f - 2.0f / (e + 1.0f);
}

__device__ __forceinline__ void grid_barrier() {
    __threadfence();           // make this CTA's global stores device-visible
    __syncthreads();
    if (threadIdx.x == 0) {
        unsigned my = g_bar_gen;
        if (atomicAdd(&g_bar_cnt, 1u) == (unsigned)(NCTA - 1)) {
            g_bar_cnt = 0;
            __threadfence();
            g_bar_gen = my + 1u;        // release
        } else {
            while (g_bar_gen == my) { } // volatile spin (L2)
        }
    }
    __syncthreads();
}

// ---------------- prep: decay transpose + zero states ----------------
__global__ void prep_kernel(const float* __restrict__ ts) {
    int i = blockIdx.x * blockDim.x + threadIdx.x;
    if (i < S_ * B_) {
        int s = i >> 6, b = i & 63;
        g_decT[i] = 1.0f / logf(2.718281828459045f + ts[b * S_ + s]);
        g_h[0][i] = 0.0f; g_h[1][i] = 0.0f;
        g_c[0][i] = 0.0f; g_c[1][i] = 0.0f;
    }
}

// ---------------- u_proj GEMM: [32768 x 256] @ [256 x 2048]^T -> g_upT[s][g][b] ----------------
#define BM 128
#define BN 128
#define BK 16
__global__ __launch_bounds__(256) void uproj_gemm(const float* __restrict__ X,
                                                  const float* __restrict__ U,
                                                  const float* __restrict__ Ub) {
    __shared__ float As[BK][BM + 4];
    __shared__ float Bs[BK][BN + 4];
    int tid = threadIdx.x;
    int m0 = blockIdx.x * BM;     // m' = s*64 + b
    int n0 = blockIdx.y * BN;
    int tm = (tid >> 4) << 3;     // 0..120
    int tn = (tid & 15) << 3;     // 0..120

    float acc[8][8];
#pragma unroll
    for (int i = 0; i < 8; i++)
#pragma unroll
        for (int j = 0; j < 8; j++) acc[i][j] = 0.0f;

    for (int k0 = 0; k0 < E_; k0 += BK) {
#pragma unroll
        for (int it = 0; it < 2; it++) {
            int t = tid + it * 256;        // 0..511
            int row = t >> 2;              // 0..127
            int kq = (t & 3) << 2;         // 0,4,8,12
            int mp = m0 + row;
            int bb = mp & 63, ssx = mp >> 6;
            float4 va = *(const float4*)(X + ((long long)bb * S_ + ssx) * E_ + k0 + kq);
            As[kq + 0][row] = va.x; As[kq + 1][row] = va.y;
            As[kq + 2][row] = va.z; As[kq + 3][row] = va.w;
            float4 vb = *(const float4*)(U + (long long)(n0 + row) * E_ + k0 + kq);
            Bs[kq + 0][row] = vb.x; Bs[kq + 1][row] = vb.y;
            Bs[kq + 2][row] = vb.z; Bs[kq + 3][row] = vb.w;
        }
        __syncthreads();
#pragma unroll
        for (int k = 0; k < BK; k++) {
            float a[8], b[8];
            *(float4*)&a[0] = *(const float4*)&As[k][tm];
            *(float4*)&a[4] = *(const float4*)&As[k][tm + 4];
            *(float4*)&b[0] = *(const float4*)&Bs[k][tn];
            *(float4*)&b[4] = *(const float4*)&Bs[k][tn + 4];
#pragma unroll
            for (int i = 0; i < 8; i++)
#pragma unroll
                for (int j = 0; j < 8; j++) acc[i][j] += a[i] * b[j];
        }
        __syncthreads();
    }

    int ssx = (m0 + tm) >> 6;
    int b0  = (m0 + tm) & 63;     // 8 consecutive b, same s
#pragma unroll
    for (int j = 0; j < 8; j++) {
        int g = n0 + tn + j;
        float ub = Ub[g];
        float4 v0, v1;
        v0.x = acc[0][j] + ub; v0.y = acc[1][j] + ub; v0.z = acc[2][j] + ub; v0.w = acc[3][j] + ub;
        v1.x = acc[4][j] + ub; v1.y = acc[5][j] + ub; v1.z = acc[6][j] + ub; v1.w = acc[7][j] + ub;
        float* dst = &g_upT[((long long)ssx * 2048 + g) * 64 + b0];
        *(float4*)dst = v0;
        *(float4*)(dst + 4) = v1;
    }
}

// ---------------- persistent recurrent kernel ----------------
// SMEM: ws[512][20] | hs[4][32][64] | cs[4][32][64] | red[4][20][64] | hn[64][4] | cn[64][4]
#define SM_WS   0
#define SM_HS   (512 * 20)
#define SM_CS   (SM_HS + 4 * 32 * 64)
#define SM_RED  (SM_CS + 4 * 32 * 64)
#define SM_HN   (SM_RED + 4 * 20 * 64)
#define SM_CN   (SM_HN + 64 * 4)
#define SM_FLOATS (SM_CN + 64 * 4)

__global__ __launch_bounds__(NTHR, 1) void step_kernel(
    const float* __restrict__ Wall, const float* __restrict__ Wallb,
    const float* __restrict__ Wd,   const float* __restrict__ Wdb,
    float* __restrict__ out)
{
    extern __shared__ float sm[];
    float* ws  = sm + SM_WS;
    float* hs  = sm + SM_HS;
    float* cs  = sm + SM_CS;
    float* red = sm + SM_RED;
    float* hn  = sm + SM_HN;
    float* cn  = sm + SM_CN;

    const int tid  = threadIdx.x;
    const int cta  = blockIdx.x;
    const int kgrp = tid / 80;          // 0..3
    const int r80  = tid % 80;
    const int rgrp = r80 / 16;          // 0..4   (0..3 -> h rows, 4 -> c rows)
    const int bgrp = r80 % 16;          // 0..15
    const int u0   = cta * 4;           // this CTA's 4 hidden units

    // ---- load this CTA's 20 weight rows into SMEM (once) ----
    for (int i = tid; i < 20 * 512; i += NTHR) {
        int rloc = i >> 9, k = i & 511;
        float w;
        if (rloc < 16) w = Wall[((rloc >> 2) * 512 + u0 + (rloc & 3)) * 512 + k];
        else           w = Wd[(u0 + (rloc - 16)) * 512 + k];
        ws[k * 20 + rloc] = w;
    }

    // ---- epilogue cell ownership: thread t<256 owns (b = t&63, ul = t>>6) ----
    const int  eb  = tid & 63;
    const int  eul = tid >> 6;
    const bool ep  = (tid < 256);
    float c_reg = 0.0f;
    float bf = 0, bi = 0, bo = 0, bct = 0, bd = 0;
    if (ep) {
        int u = u0 + eul;
        bf  = Wallb[u];
        bi  = Wallb[512 + u];
        bo  = Wallb[1024 + u];
        bct = Wallb[1536 + u];
        bd  = Wdb[u];
    }
    __syncthreads();

    const float* apool = (rgrp < 4) ? hs : cs;
    const int aoff = kgrp * 32 * 64 + bgrp * 4;
    const int woff = rgrp * 4;

    for (int s = 0; s < S_; s++) {
        const int par = s & 1;
        const float* gh = g_h[par];
        const float* gc = g_c[par];

        float acc[4][4];
#pragma unroll
        for (int i = 0; i < 4; i++)
#pragma unroll
            for (int j = 0; j < 4; j++) acc[i][j] = 0.0f;

        for (int kc = 0; kc < 128; kc += 32) {
            __syncthreads();
            // stage hT/cT chunk: [4 kgrp][32 k][64 b], bypass L1 (cross-CTA data)
            for (int i = tid; i < 2048; i += NTHR) {
                int kg = i >> 9, rem = i & 511;
                int kk = rem >> 4, b4 = (rem & 15) << 2;
                int gidx = (kg * 128 + kc + kk) * 64 + b4;
                *(float4*)&hs[kg * 2048 + kk * 64 + b4] = __ldcg((const float4*)&gh[gidx]);
                *(float4*)&cs[kg * 2048 + kk * 64 + b4] = __ldcg((const float4*)&gc[gidx]);
            }
            __syncthreads();
#pragma unroll
            for (int kk = 0; kk < 32; kk++) {
                float4 a4 = *(const float4*)&apool[aoff + kk * 64];
                float4 w4 = *(const float4*)&ws[(kgrp * 128 + kc + kk) * 20 + woff];
                float av[4] = {a4.x, a4.y, a4.z, a4.w};
                float wv[4] = {w4.x, w4.y, w4.z, w4.w};
#pragma unroll
                for (int i = 0; i < 4; i++)
#pragma unroll
                    for (int j = 0; j < 4; j++) acc[i][j] += av[i] * wv[j];
            }
        }

        // ---- K-group reduce via SMEM ----
#pragma unroll
        for (int j = 0; j < 4; j++) {
            float4 v;
            v.x = acc[0][j]; v.y = acc[1][j]; v.z = acc[2][j]; v.w = acc[3][j];
            *(float4*)&red[(kgrp * 20 + rgrp * 4 + j) * 64 + bgrp * 4] = v;
        }
        __syncthreads();

        // ---- fused LSTM update epilogue ----
        if (ep) {
            int u = u0 + eul;
            float gsum[5];
#pragma unroll
            for (int g5 = 0; g5 < 5; g5++) {
                int rl = (g5 < 4) ? (g5 * 4 + eul) : (16 + eul);
                float v = 0.0f;
#pragma unroll
                for (int kg = 0; kg < 4; kg++) v += red[(kg * 20 + rl) * 64 + eb];
                gsum[g5] = v;
            }
            float dec = g_decT[s * 64 + eb];
            const float* up = &g_upT[(long long)s * 2048 * 64];
            float upf = up[(0 * 512 + u) * 64 + eb];
            float upi = up[(1 * 512 + u) * 64 + eb];
            float upo = up[(2 * 512 + u) * 64 + eb];
            float upc = up[(3 * 512 + u) * 64 + eb];

            float cs1  = tanh_fast(gsum[4] + bd);
            float cadj = (c_reg - cs1) + cs1 * dec;
            float f  = sigf(gsum[0] + bf + upf);
            float ii = sigf(gsum[1] + bi + upi);
            float oo = sigf(gsum[2] + bo + upo);
            float ct = tanh_fast(gsum[3] + bct + upc);
            float cnew = f * cadj + ii * ct;
            float hnew = oo * tanh_fast(cnew);
            c_reg = cnew;

            int par2 = par ^ 1;
            __stcg(&g_h[par2][u * 64 + eb], hnew);
            __stcg(&g_c[par2][u * 64 + eb], cnew);
            hn[eb * 4 + eul] = hnew;
            cn[eb * 4 + eul] = cnew;
        }
        __syncthreads();

        // coalesced-ish output writes via SMEM bounce (16B per store)
        if (tid < 64) {
            float4 hv = *(float4*)&hn[tid * 4];
            *(float4*)&out[((long long)tid * S_ + s) * H_ + u0] = hv;
            if (s == S_ - 1) {
                float4 cv = *(float4*)&cn[tid * 4];
                *(float4*)&out[(long long)B_ * S_ * H_ + (long long)tid * H_ + u0] = hv;
                *(float4*)&out[(long long)B_ * S_ * H_ + (long long)B_ * H_ + (long long)tid * H_ + u0] = cv;
            }
        }

        grid_barrier();   // h/c parity buffers published for next step
    }
}

// ---------------- launcher ----------------
extern "C" void kernel_launch(void* const* d_in, const int* in_sizes, int n_in,
                              void* d_out, int out_size) {
    const float* inputs = (const float*)d_in[0];
    const float* ts     = (const float*)d_in[1];
    const float* Wall   = (const float*)d_in[2];
    const float* Wallb  = (const float*)d_in[3];
    const float* U      = (const float*)d_in[4];
    const float* Ub     = (const float*)d_in[5];
    const float* Wd     = (const float*)d_in[6];
    const float* Wdb    = (const float*)d_in[7];
    float* out = (float*)d_out;

    prep_kernel<<<(S_ * B_ + 255) / 256, 256>>>(ts);

    dim3 ggrid(32768 / BM, 2048 / BN);
    uproj_gemm<<<ggrid, 256>>>(inputs, U, Ub);

    static const size_t smem_bytes = (size_t)SM_FLOATS * sizeof(float);  // ~129 KB
    cudaFuncSetAttribute(step_kernel, cudaFuncAttributeMaxDynamicSharedMemorySize,
                         (int)smem_bytes);
    step_kernel<<<NCTA, NTHR, smem_bytes>>>(Wall, Wallb, Wd, Wdb, out);
}

// round 8
// speedup vs baseline: 1.0016x; 1.0016x over previous
#include <cuda_runtime.h>
#include <math.h>

#define B_    64
#define S_    512
#define E_    256
#define H_    512
#define NCTA  128
#define NTHR  320

// ---------------- device scratch (static; no allocation) ----------------
__device__ float g_upT[(long long)S_ * 2048 * B_];   // [s][g][b]  256 MB
__device__ float g_decT[S_ * B_];                    // [s][b]
__device__ float g_h[2][H_ * B_];                    // [par][u][b]
__device__ float g_c[2][H_ * B_];
__device__ volatile unsigned g_bar_gen;
__device__ unsigned g_bar_cnt;

// ---------------- helpers ----------------
__device__ __forceinline__ float sigf(float x) { return 1.0f / (1.0f + __expf(-x)); }
__device__ __forceinline__ float tanh_fast(float x) {
    float e = __expf(2.0f * x);
    return 1.0f - 2.0f / (e + 1.0f);
}

__device__ __forceinline__ void grid_barrier() {
    __threadfence();           // make this CTA's global stores device-visible
    __syncthreads();
    if (threadIdx.x == 0) {
        unsigned my = g_bar_gen;
        if (atomicAdd(&g_bar_cnt, 1u) == (unsigned)(NCTA - 1)) {
            g_bar_cnt = 0;
            __threadfence();
            g_bar_gen = my + 1u;        // release
        } else {
            while (g_bar_gen == my) { } // volatile spin (L2)
        }
    }
    __syncthreads();
}

// ---------------- prep: decay transpose + zero states ----------------
__global__ void prep_kernel(const float* __restrict__ ts) {
    int i = blockIdx.x * blockDim.x + threadIdx.x;
    if (i < S_ * B_) {
        int s = i >> 6, b = i & 63;
        g_decT[i] = 1.0f / logf(2.718281828459045f + ts[b * S_ + s]);
        g_h[0][i] = 0.0f; g_h[1][i] = 0.0f;
        g_c[0][i] = 0.0f; g_c[1][i] = 0.0f;
    }
}

// ---------------- u_proj GEMM: [32768 x 256] @ [256 x 2048]^T -> g_upT[s][g][b] ----------------
#define BM 128
#define BN 128
#define BK 16
__global__ __launch_bounds__(256) void uproj_gemm(const float* __restrict__ X,
                                                  const float* __restrict__ U,
                                                  const float* __restrict__ Ub) {
    __shared__ float As[BK][BM + 4];
    __shared__ float Bs[BK][BN + 4];
    int tid = threadIdx.x;
    int m0 = blockIdx.x * BM;     // m' = s*64 + b
    int n0 = blockIdx.y * BN;
    int tm = (tid >> 4) << 3;     // 0..120
    int tn = (tid & 15) << 3;     // 0..120

    float acc[8][8];
#pragma unroll
    for (int i = 0; i < 8; i++)
#pragma unroll
        for (int j = 0; j < 8; j++) acc[i][j] = 0.0f;

    for (int k0 = 0; k0 < E_; k0 += BK) {
#pragma unroll
        for (int it = 0; it < 2; it++) {
            int t = tid + it * 256;        // 0..511
            int row = t >> 2;              // 0..127
            int kq = (t & 3) << 2;         // 0,4,8,12
            int mp = m0 + row;
            int bb = mp & 63, ssx = mp >> 6;
            float4 va = *(const float4*)(X + ((long long)bb * S_ + ssx) * E_ + k0 + kq);
            As[kq + 0][row] = va.x; As[kq + 1][row] = va.y;
            As[kq + 2][row] = va.z; As[kq + 3][row] = va.w;
            float4 vb = *(const float4*)(U + (long long)(n0 + row) * E_ + k0 + kq);
            Bs[kq + 0][row] = vb.x; Bs[kq + 1][row] = vb.y;
            Bs[kq + 2][row] = vb.z; Bs[kq + 3][row] = vb.w;
        }
        __syncthreads();
#pragma unroll
        for (int k = 0; k < BK; k++) {
            float a[8], b[8];
            *(float4*)&a[0] = *(const float4*)&As[k][tm];
            *(float4*)&a[4] = *(const float4*)&As[k][tm + 4];
            *(float4*)&b[0] = *(const float4*)&Bs[k][tn];
            *(float4*)&b[4] = *(const float4*)&Bs[k][tn + 4];
#pragma unroll
            for (int i = 0; i < 8; i++)
#pragma unroll
                for (int j = 0; j < 8; j++) acc[i][j] += a[i] * b[j];
        }
        __syncthreads();
    }

    int ssx = (m0 + tm) >> 6;
    int b0  = (m0 + tm) & 63;     // 8 consecutive b, same s
#pragma unroll
    for (int j = 0; j < 8; j++) {
        int g = n0 + tn + j;
        float ub = Ub[g];
        float4 v0, v1;
        v0.x = acc[0][j] + ub; v0.y = acc[1][j] + ub; v0.z = acc[2][j] + ub; v0.w = acc[3][j] + ub;
        v1.x = acc[4][j] + ub; v1.y = acc[5][j] + ub; v1.z = acc[6][j] + ub; v1.w = acc[7][j] + ub;
        float* dst = &g_upT[((long long)ssx * 2048 + g) * 64 + b0];
        *(float4*)dst = v0;
        *(float4*)(dst + 4) = v1;
    }
}

// ---------------- persistent recurrent kernel ----------------
// SMEM: ws[512][20] | hs[4][32][64] | cs[4][32][64] | red[4][20][64] | hn[64][4] | cn[64][4]
#define SM_WS   0
#define SM_HS   (512 * 20)
#define SM_CS   (SM_HS + 4 * 32 * 64)
#define SM_RED  (SM_CS + 4 * 32 * 64)
#define SM_HN   (SM_RED + 4 * 20 * 64)
#define SM_CN   (SM_HN + 64 * 4)
#define SM_FLOATS (SM_CN + 64 * 4)

__global__ __launch_bounds__(NTHR, 1) void step_kernel(
    const float* __restrict__ Wall, const float* __restrict__ Wallb,
    const float* __restrict__ Wd,   const float* __restrict__ Wdb,
    float* __restrict__ out)
{
    extern __shared__ float sm[];
    float* ws  = sm + SM_WS;
    float* hs  = sm + SM_HS;
    float* cs  = sm + SM_CS;
    float* red = sm + SM_RED;
    float* hn  = sm + SM_HN;
    float* cn  = sm + SM_CN;

    const int tid  = threadIdx.x;
    const int cta  = blockIdx.x;
    const int kgrp = tid / 80;          // 0..3
    const int r80  = tid % 80;
    const int rgrp = r80 / 16;          // 0..4   (0..3 -> h rows, 4 -> c rows)
    const int bgrp = r80 % 16;          // 0..15
    const int u0   = cta * 4;           // this CTA's 4 hidden units

    // ---- load this CTA's 20 weight rows into SMEM (once) ----
    for (int i = tid; i < 20 * 512; i += NTHR) {
        int rloc = i >> 9, k = i & 511;
        float w;
        if (rloc < 16) w = Wall[((rloc >> 2) * 512 + u0 + (rloc & 3)) * 512 + k];
        else           w = Wd[(u0 + (rloc - 16)) * 512 + k];
        ws[k * 20 + rloc] = w;
    }

    // ---- epilogue cell ownership: thread t<256 owns (b = t&63, ul = t>>6) ----
    const int  eb  = tid & 63;
    const int  eul = tid >> 6;
    const bool ep  = (tid < 256);
    float c_reg = 0.0f;
    float bf = 0, bi = 0, bo = 0, bct = 0, bd = 0;
    if (ep) {
        int u = u0 + eul;
        bf  = Wallb[u];
        bi  = Wallb[512 + u];
        bo  = Wallb[1024 + u];
        bct = Wallb[1536 + u];
        bd  = Wdb[u];
    }
    __syncthreads();

    const float* apool = (rgrp < 4) ? hs : cs;
    const int aoff = kgrp * 32 * 64 + bgrp * 4;
    const int woff = rgrp * 4;

    for (int s = 0; s < S_; s++) {
        const int par = s & 1;
        const float* gh = g_h[par];
        const float* gc = g_c[par];

        float acc[4][4];
#pragma unroll
        for (int i = 0; i < 4; i++)
#pragma unroll
            for (int j = 0; j < 4; j++) acc[i][j] = 0.0f;

        for (int kc = 0; kc < 128; kc += 32) {
            __syncthreads();
            // stage hT/cT chunk: [4 kgrp][32 k][64 b], bypass L1 (cross-CTA data)
            for (int i = tid; i < 2048; i += NTHR) {
                int kg = i >> 9, rem = i & 511;
                int kk = rem >> 4, b4 = (rem & 15) << 2;
                int gidx = (kg * 128 + kc + kk) * 64 + b4;
                *(float4*)&hs[kg * 2048 + kk * 64 + b4] = __ldcg((const float4*)&gh[gidx]);
                *(float4*)&cs[kg * 2048 + kk * 64 + b4] = __ldcg((const float4*)&gc[gidx]);
            }
            __syncthreads();
#pragma unroll
            for (int kk = 0; kk < 32; kk++) {
                float4 a4 = *(const float4*)&apool[aoff + kk * 64];
                float4 w4 = *(const float4*)&ws[(kgrp * 128 + kc + kk) * 20 + woff];
                float av[4] = {a4.x, a4.y, a4.z, a4.w};
                float wv[4] = {w4.x, w4.y, w4.z, w4.w};
#pragma unroll
                for (int i = 0; i < 4; i++)
#pragma unroll
                    for (int j = 0; j < 4; j++) acc[i][j] += av[i] * wv[j];
            }
        }

        // ---- K-group reduce via SMEM ----
#pragma unroll
        for (int j = 0; j < 4; j++) {
            float4 v;
            v.x = acc[0][j]; v.y = acc[1][j]; v.z = acc[2][j]; v.w = acc[3][j];
            *(float4*)&red[(kgrp * 20 + rgrp * 4 + j) * 64 + bgrp * 4] = v;
        }
        __syncthreads();

        // ---- fused LSTM update epilogue ----
        if (ep) {
            int u = u0 + eul;
            float gsum[5];
#pragma unroll
            for (int g5 = 0; g5 < 5; g5++) {
                int rl = (g5 < 4) ? (g5 * 4 + eul) : (16 + eul);
                float v = 0.0f;
#pragma unroll
                for (int kg = 0; kg < 4; kg++) v += red[(kg * 20 + rl) * 64 + eb];
                gsum[g5] = v;
            }
            float dec = g_decT[s * 64 + eb];
            const float* up = &g_upT[(long long)s * 2048 * 64];
            float upf = up[(0 * 512 + u) * 64 + eb];
            float upi = up[(1 * 512 + u) * 64 + eb];
            float upo = up[(2 * 512 + u) * 64 + eb];
            float upc = up[(3 * 512 + u) * 64 + eb];

            float cs1  = tanh_fast(gsum[4] + bd);
            float cadj = (c_reg - cs1) + cs1 * dec;
            float f  = sigf(gsum[0] + bf + upf);
            float ii = sigf(gsum[1] + bi + upi);
            float oo = sigf(gsum[2] + bo + upo);
            float ct = tanh_fast(gsum[3] + bct + upc);
            float cnew = f * cadj + ii * ct;
            float hnew = oo * tanh_fast(cnew);
            c_reg = cnew;

            int par2 = par ^ 1;
            __stcg(&g_h[par2][u * 64 + eb], hnew);
            __stcg(&g_c[par2][u * 64 + eb], cnew);
            hn[eb * 4 + eul] = hnew;
            cn[eb * 4 + eul] = cnew;
        }
        __syncthreads();

        // coalesced-ish output writes via SMEM bounce (16B per store)
        if (tid < 64) {
            float4 hv = *(float4*)&hn[tid * 4];
            *(float4*)&out[((long long)tid * S_ + s) * H_ + u0] = hv;
            if (s == S_ - 1) {
                float4 cv = *(float4*)&cn[tid * 4];
                *(float4*)&out[(long long)B_ * S_ * H_ + (long long)tid * H_ + u0] = hv;
                *(float4*)&out[(long long)B_ * S_ * H_ + (long long)B_ * H_ + (long long)tid * H_ + u0] = cv;
            }
        }

        grid_barrier();   // h/c parity buffers published for next step
    }
}

// ---------------- launcher ----------------
extern "C" void kernel_launch(void* const* d_in, const int* in_sizes, int n_in,
                              void* d_out, int out_size) {
    const float* inputs = (const float*)d_in[0];
    const float* ts     = (const float*)d_in[1];
    const float* Wall   = (const float*)d_in[2];
    const float* Wallb  = (const float*)d_in[3];
    const float* U      = (const float*)d_in[4];
    const float* Ub     = (const float*)d_in[5];
    const float* Wd     = (const float*)d_in[6];
    const float* Wdb    = (const float*)d_in[7];
    float* out = (float*)d_out;

    prep_kernel<<<(S_ * B_ + 255) / 256, 256>>>(ts);

    dim3 ggrid(32768 / BM, 2048 / BN);
    uproj_gemm<<<ggrid, 256>>>(inputs, U, Ub);

    static const size_t smem_bytes = (size_t)SM_FLOATS * sizeof(float);  // ~129 KB
    cudaFuncSetAttribute(step_kernel, cudaFuncAttributeMaxDynamicSharedMemorySize,
                         (int)smem_bytes);
    step_kernel<<<NCTA, NTHR, smem_bytes>>>(Wall, Wallb, Wd, Wdb, out);
}

// round 11
// speedup vs baseline: 1.0019x; 1.0003x over previous
#include <cuda_runtime.h>
#include <math.h>

#define B_    64
#define S_    512
#define E_    256
#define H_    512
#define NCTA  128
#define NTHR  320

// ---------------- device scratch (static; no allocation) ----------------
__device__ float g_upT[(long long)S_ * 2048 * B_];   // [s][g][b]  256 MB
__device__ float g_decT[S_ * B_];                    // [s][b]
__device__ float g_h[2][H_ * B_];                    // [par][u][b]
__device__ float g_c[2][H_ * B_];
__device__ volatile unsigned g_bar_gen;
__device__ unsigned g_bar_cnt;

// ---------------- helpers ----------------
__device__ __forceinline__ float sigf(float x) { return 1.0f / (1.0f + __expf(-x)); }
__device__ __forceinline__ float tanh_fast(float x) {
    float e = __expf(2.0f * x);
    return 1.0f - 2.0f / (e + 1.0f);
}

__device__ __forceinline__ void grid_barrier() {
    __threadfence();           // make this CTA's global stores device-visible
    __syncthreads();
    if (threadIdx.x == 0) {
        unsigned my = g_bar_gen;
        if (atomicAdd(&g_bar_cnt, 1u) == (unsigned)(NCTA - 1)) {
            g_bar_cnt = 0;
            __threadfence();
            g_bar_gen = my + 1u;        // release
        } else {
            while (g_bar_gen == my) { } // volatile spin (L2)
        }
    }
    __syncthreads();
}

// ---------------- prep: decay transpose + zero states ----------------
__global__ void prep_kernel(const float* __restrict__ ts) {
    int i = blockIdx.x * blockDim.x + threadIdx.x;
    if (i < S_ * B_) {
        int s = i >> 6, b = i & 63;
        g_decT[i] = 1.0f / logf(2.718281828459045f + ts[b * S_ + s]);
        g_h[0][i] = 0.0f; g_h[1][i] = 0.0f;
        g_c[0][i] = 0.0f; g_c[1][i] = 0.0f;
    }
}

// ---------------- u_proj GEMM: [32768 x 256] @ [256 x 2048]^T -> g_upT[s][g][b] ----------------
#define BM 128
#define BN 128
#define BK 16
__global__ __launch_bounds__(256) void uproj_gemm(const float* __restrict__ X,
                                                  const float* __restrict__ U,
                                                  const float* __restrict__ Ub) {
    __shared__ float As[BK][BM + 4];
    __shared__ float Bs[BK][BN + 4];
    int tid = threadIdx.x;
    int m0 = blockIdx.x * BM;     // m' = s*64 + b
    int n0 = blockIdx.y * BN;
    int tm = (tid >> 4) << 3;     // 0..120
    int tn = (tid & 15) << 3;     // 0..120

    float acc[8][8];
#pragma unroll
    for (int i = 0; i < 8; i++)
#pragma unroll
        for (int j = 0; j < 8; j++) acc[i][j] = 0.0f;

    for (int k0 = 0; k0 < E_; k0 += BK) {
#pragma unroll
        for (int it = 0; it < 2; it++) {
            int t = tid + it * 256;        // 0..511
            int row = t >> 2;              // 0..127
            int kq = (t & 3) << 2;         // 0,4,8,12
            int mp = m0 + row;
            int bb = mp & 63, ssx = mp >> 6;
            float4 va = *(const float4*)(X + ((long long)bb * S_ + ssx) * E_ + k0 + kq);
            As[kq + 0][row] = va.x; As[kq + 1][row] = va.y;
            As[kq + 2][row] = va.z; As[kq + 3][row] = va.w;
            float4 vb = *(const float4*)(U + (long long)(n0 + row) * E_ + k0 + kq);
            Bs[kq + 0][row] = vb.x; Bs[kq + 1][row] = vb.y;
            Bs[kq + 2][row] = vb.z; Bs[kq + 3][row] = vb.w;
        }
        __syncthreads();
#pragma unroll
        for (int k = 0; k < BK; k++) {
            float a[8], b[8];
            *(float4*)&a[0] = *(const float4*)&As[k][tm];
            *(float4*)&a[4] = *(const float4*)&As[k][tm + 4];
            *(float4*)&b[0] = *(const float4*)&Bs[k][tn];
            *(float4*)&b[4] = *(const float4*)&Bs[k][tn + 4];
#pragma unroll
            for (int i = 0; i < 8; i++)
#pragma unroll
                for (int j = 0; j < 8; j++) acc[i][j] += a[i] * b[j];
        }
        __syncthreads();
    }

    int ssx = (m0 + tm) >> 6;
    int b0  = (m0 + tm) & 63;     // 8 consecutive b, same s
#pragma unroll
    for (int j = 0; j < 8; j++) {
        int g = n0 + tn + j;
        float ub = Ub[g];
        float4 v0, v1;
        v0.x = acc[0][j] + ub; v0.y = acc[1][j] + ub; v0.z = acc[2][j] + ub; v0.w = acc[3][j] + ub;
        v1.x = acc[4][j] + ub; v1.y = acc[5][j] + ub; v1.z = acc[6][j] + ub; v1.w = acc[7][j] + ub;
        float* dst = &g_upT[((long long)ssx * 2048 + g) * 64 + b0];
        *(float4*)dst = v0;
        *(float4*)(dst + 4) = v1;
    }
}

// ---------------- persistent recurrent kernel ----------------
// SMEM: ws[512][20] | hs[4][32][64] | cs[4][32][64] | red[4][20][64] | hn[64][4] | cn[64][4]
#define SM_WS   0
#define SM_HS   (512 * 20)
#define SM_CS   (SM_HS + 4 * 32 * 64)
#define SM_RED  (SM_CS + 4 * 32 * 64)
#define SM_HN   (SM_RED + 4 * 20 * 64)
#define SM_CN   (SM_HN + 64 * 4)
#define SM_FLOATS (SM_CN + 64 * 4)

__global__ __launch_bounds__(NTHR, 1) void step_kernel(
    const float* __restrict__ Wall, const float* __restrict__ Wallb,
    const float* __restrict__ Wd,   const float* __restrict__ Wdb,
    float* __restrict__ out)
{
    extern __shared__ float sm[];
    float* ws  = sm + SM_WS;
    float* hs  = sm + SM_HS;
    float* cs  = sm + SM_CS;
    float* red = sm + SM_RED;
    float* hn  = sm + SM_HN;
    float* cn  = sm + SM_CN;

    const int tid  = threadIdx.x;
    const int cta  = blockIdx.x;
    const int kgrp = tid / 80;          // 0..3
    const int r80  = tid % 80;
    const int rgrp = r80 / 16;          // 0..4   (0..3 -> h rows, 4 -> c rows)
    const int bgrp = r80 % 16;          // 0..15
    const int u0   = cta * 4;           // this CTA's 4 hidden units

    // ---- load this CTA's 20 weight rows into SMEM (once) ----
    for (int i = tid; i < 20 * 512; i += NTHR) {
        int rloc = i >> 9, k = i & 511;
        float w;
        if (rloc < 16) w = Wall[((rloc >> 2) * 512 + u0 + (rloc & 3)) * 512 + k];
        else           w = Wd[(u0 + (rloc - 16)) * 512 + k];
        ws[k * 20 + rloc] = w;
    }

    // ---- epilogue cell ownership: thread t<256 owns (b = t&63, ul = t>>6) ----
    const int  eb  = tid & 63;
    const int  eul = tid >> 6;
    const bool ep  = (tid < 256);
    float c_reg = 0.0f;
    float bf = 0, bi = 0, bo = 0, bct = 0, bd = 0;
    if (ep) {
        int u = u0 + eul;
        bf  = Wallb[u];
        bi  = Wallb[512 + u];
        bo  = Wallb[1024 + u];
        bct = Wallb[1536 + u];
        bd  = Wdb[u];
    }
    __syncthreads();

    const float* apool = (rgrp < 4) ? hs : cs;
    const int aoff = kgrp * 32 * 64 + bgrp * 4;
    const int woff = rgrp * 4;

    for (int s = 0; s < S_; s++) {
        const int par = s & 1;
        const float* gh = g_h[par];
        const float* gc = g_c[par];

        float acc[4][4];
#pragma unroll
        for (int i = 0; i < 4; i++)
#pragma unroll
            for (int j = 0; j < 4; j++) acc[i][j] = 0.0f;

        for (int kc = 0; kc < 128; kc += 32) {
            __syncthreads();
            // stage hT/cT chunk: [4 kgrp][32 k][64 b], bypass L1 (cross-CTA data)
            for (int i = tid; i < 2048; i += NTHR) {
                int kg = i >> 9, rem = i & 511;
                int kk = rem >> 4, b4 = (rem & 15) << 2;
                int gidx = (kg * 128 + kc + kk) * 64 + b4;
                *(float4*)&hs[kg * 2048 + kk * 64 + b4] = __ldcg((const float4*)&gh[gidx]);
                *(float4*)&cs[kg * 2048 + kk * 64 + b4] = __ldcg((const float4*)&gc[gidx]);
            }
            __syncthreads();
#pragma unroll
            for (int kk = 0; kk < 32; kk++) {
                float4 a4 = *(const float4*)&apool[aoff + kk * 64];
                float4 w4 = *(const float4*)&ws[(kgrp * 128 + kc + kk) * 20 + woff];
                float av[4] = {a4.x, a4.y, a4.z, a4.w};
                float wv[4] = {w4.x, w4.y, w4.z, w4.w};
#pragma unroll
                for (int i = 0; i < 4; i++)
#pragma unroll
                    for (int j = 0; j < 4; j++) acc[i][j] += av[i] * wv[j];
            }
        }

        // ---- K-group reduce via SMEM ----
#pragma unroll
        for (int j = 0; j < 4; j++) {
            float4 v;
            v.x = acc[0][j]; v.y = acc[1][j]; v.z = acc[2][j]; v.w = acc[3][j];
            *(float4*)&red[(kgrp * 20 + rgrp * 4 + j) * 64 + bgrp * 4] = v;
        }
        __syncthreads();

        // ---- fused LSTM update epilogue ----
        if (ep) {
            int u = u0 + eul;
            float gsum[5];
#pragma unroll
            for (int g5 = 0; g5 < 5; g5++) {
                int rl = (g5 < 4) ? (g5 * 4 + eul) : (16 + eul);
                float v = 0.0f;
#pragma unroll
                for (int kg = 0; kg < 4; kg++) v += red[(kg * 20 + rl) * 64 + eb];
                gsum[g5] = v;
            }
            float dec = g_decT[s * 64 + eb];
            const float* up = &g_upT[(long long)s * 2048 * 64];
            float upf = up[(0 * 512 + u) * 64 + eb];
            float upi = up[(1 * 512 + u) * 64 + eb];
            float upo = up[(2 * 512 + u) * 64 + eb];
            float upc = up[(3 * 512 + u) * 64 + eb];

            float cs1  = tanh_fast(gsum[4] + bd);
            float cadj = (c_reg - cs1) + cs1 * dec;
            float f  = sigf(gsum[0] + bf + upf);
            float ii = sigf(gsum[1] + bi + upi);
            float oo = sigf(gsum[2] + bo + upo);
            float ct = tanh_fast(gsum[3] + bct + upc);
            float cnew = f * cadj + ii * ct;
            float hnew = oo * tanh_fast(cnew);
            c_reg = cnew;

            int par2 = par ^ 1;
            __stcg(&g_h[par2][u * 64 + eb], hnew);
            __stcg(&g_c[par2][u * 64 + eb], cnew);
            hn[eb * 4 + eul] = hnew;
            cn[eb * 4 + eul] = cnew;
        }
        __syncthreads();

        // coalesced-ish output writes via SMEM bounce (16B per store)
        if (tid < 64) {
            float4 hv = *(float4*)&hn[tid * 4];
            *(float4*)&out[((long long)tid * S_ + s) * H_ + u0] = hv;
            if (s == S_ - 1) {
                float4 cv = *(float4*)&cn[tid * 4];
                *(float4*)&out[(long long)B_ * S_ * H_ + (long long)tid * H_ + u0] = hv;
                *(float4*)&out[(long long)B_ * S_ * H_ + (long long)B_ * H_ + (long long)tid * H_ + u0] = cv;
            }
        }

        grid_barrier();   // h/c parity buffers published for next step
    }
}

// ---------------- launcher ----------------
extern "C" void kernel_launch(void* const* d_in, const int* in_sizes, int n_in,
                              void* d_out, int out_size) {
    const float* inputs = (const float*)d_in[0];
    const float* ts     = (const float*)d_in[1];
    const float* Wall   = (const float*)d_in[2];
    const float* Wallb  = (const float*)d_in[3];
    const float* U      = (const float*)d_in[4];
    const float* Ub     = (const float*)d_in[5];
    const float* Wd     = (const float*)d_in[6];
    const float* Wdb    = (const float*)d_in[7];
    float* out = (float*)d_out;

    prep_kernel<<<(S_ * B_ + 255) / 256, 256>>>(ts);

    dim3 ggrid(32768 / BM, 2048 / BN);
    uproj_gemm<<<ggrid, 256>>>(inputs, U, Ub);

    static const size_t smem_bytes = (size_t)SM_FLOATS * sizeof(float);  // ~129 KB
    cudaFuncSetAttribute(step_kernel, cudaFuncAttributeMaxDynamicSharedMemorySize,
                         (int)smem_bytes);
    step_kernel<<<NCTA, NTHR, smem_bytes>>>(Wall, Wallb, Wd, Wdb, out);
}